// round 14
// baseline (speedup 1.0000x reference)
#include <cuda_runtime.h>
#include <cuda_fp16.h>
#include <math.h>

#define N_NODES 100000
#define N_EDGES 1600000
#define MAX_ITER 50
#define THRESH 0.01f

#define BNBLK 148                            // build kernel blocks
#define BTHR 1024
#define BWPB (BTHR / 32)
#define BNWARPS (BNBLK * BWPB)
#define MNBLK 296                            // main kernel blocks (2/SM)
#define MTHR 768
#define MWPB (MTHR / 32)
#define MNWARPS (MNBLK * MWPB)               // 7104 warps = 48/SM
#define NGROUPS (N_EDGES / 32)               // 50000 exact
#define BNODE_CHUNK ((N_NODES + BNBLK - 1) / BNBLK)   // 676
#define MNODE_CHUNK ((N_NODES + MNBLK - 1) / MNBLK)   // 338
#define FULLM 0xffffffffu

typedef unsigned long long ull;

// all weights in one constant block (single D2D memcpy)
struct CW {
    float2 W1s[40];   // W1 rows 8..12, j-paired: [i=5][jp=8]
    float2 W2u[40];   // [p=8][k=5]: (W2[2p][k], W2[2p+1][k] or 0)
    float  B2[5];
    float  W3[50], B3[10], W4[70], B4[7];
};
__constant__ CW cw;

// ---- static device scratch ----
__device__ unsigned g_arrive;               // build-kernel barrier counter
__device__ unsigned g_arrive2;              // main-kernel barrier counter
__device__ uint4  g_stateh[N_NODES];        // state as fp16 (5 used of 8)
__device__ float4 g_acc4[N_NODES * 2];      // fp32 accumulator, stride 8
__device__ int    g_flag_arr[MAX_ITER + 2];
__device__ int    g_cnt[N_NODES];
__device__ int    g_cur[N_NODES];
__device__ int    g_part[BNBLK];
__device__ int    g_eord[N_EDGES];
__device__ uint4  g_pre1h[N_EDGES * 2];     // (b1 + ef@W1[0:8]) fp16 j-pairs, 32B/edge
__device__ int2   g_sa[N_EDGES];            // {src, av bits}
__device__ int    g_rowp[N_EDGES];          // row | segoff<<18 | tail<<23
__device__ float  g_stage[304];

// single-MUFU tanh (abs err ~5e-4)
__device__ __forceinline__ float tanha(float x) {
    float r; asm("tanh.approx.f32 %0, %1;" : "=f"(r) : "f"(x)); return r;
}
__device__ __forceinline__ ull pack2(float x) {
    ull r; asm("mov.b64 %0, {%1, %1};" : "=l"(r) : "f"(x)); return r;
}
__device__ __forceinline__ ull pack2f(float lo, float hi) {
    ull r; asm("mov.b64 %0, {%1, %2};" : "=l"(r) : "f"(lo), "f"(hi)); return r;
}
__device__ __forceinline__ ull fma2(ull a, ull b, ull c) {
    ull r; asm("fma.rn.f32x2 %0, %1, %2, %3;" : "=l"(r) : "l"(a), "l"(b), "l"(c)); return r;
}
__device__ __forceinline__ ull add2(ull a, ull b) {
    ull r; asm("add.rn.f32x2 %0, %1, %2;" : "=l"(r) : "l"(a), "l"(b)); return r;
}
__device__ __forceinline__ void unpack2(ull v, float& lo, float& hi) {
    asm("mov.b64 {%0, %1}, %2;" : "=f"(lo), "=f"(hi) : "l"(v));
}

// grid barrier: release-arrive + acquire-spin; monotonic counter, no reset.
// counter must be used with a CONSISTENT nblk (invariant: multiple of nblk
// between barriers) — hence separate counters for build and main kernels.
__device__ __forceinline__ void gsyncN(unsigned* ctr, unsigned nblk) {
    __syncthreads();
    if (threadIdx.x == 0) {
        unsigned old;
        asm volatile("atom.add.release.gpu.global.u32 %0, [%1], 1;"
                     : "=r"(old) : "l"(ctr) : "memory");
        unsigned tgt = (old / nblk + 1u) * nblk;
        unsigned cur;
        do {
            asm volatile("ld.acquire.gpu.global.u32 %0, [%1];"
                         : "=r"(cur) : "l"(ctr) : "memory");
        } while (cur < tgt);
    }
    __syncthreads();
}

// ===== one persistent build kernel (148 x 1024) =====
__global__ __launch_bounds__(BTHR, 1)
void build_k(const float* __restrict__ ef, const int* __restrict__ src,
             const int* __restrict__ rows, const float* __restrict__ avals,
             const float* __restrict__ W1, const float* __restrict__ b1,
             const float* __restrict__ W2, const float* __restrict__ b2,
             const float* __restrict__ W3, const float* __restrict__ b3,
             const float* __restrict__ W4, const float* __restrict__ b4) {
    __shared__ int sarr[BTHR];
    __shared__ int spart[BNBLK];
    __shared__ float2 sW1a[64];   // W1 rows 0..7, j-paired [i8][jp]
    __shared__ float2 sB1a[8];    // b1 j-paired
    const int tid = threadIdx.x, bid = blockIdx.x;
    const int gsz = BNBLK * BTHR;
    const int gi = bid * BTHR + tid;

    // phase 0: zero counters/flags, stage smem W1a/b1, stage constants
    for (int n = gi; n < N_NODES; n += gsz) g_cnt[n] = 0;
    if (gi < MAX_ITER + 2) g_flag_arr[gi] = 0;
    if (tid < 64) {
        int i8 = tid >> 3, jp = tid & 7;
        int j0 = jp * 2, j1 = j0 + 1;
        sW1a[tid] = make_float2(W1[i8 * 15 + j0],
                                (j1 < 15) ? W1[i8 * 15 + j1] : 0.f);
    } else if (tid < 72) {
        int jp = tid - 64;
        int j0 = jp * 2, j1 = j0 + 1;
        sB1a[jp] = make_float2(b1[j0], (j1 < 15) ? b1[j1] : 0.f);
    }
    if (bid == 0) {
        for (int q = tid; q < 40; q += BTHR) {          // W1 rows 8..12
            int i = 8 + (q >> 3), jp = q & 7;
            int j0 = jp * 2, j1 = j0 + 1;
            g_stage[2 * q]     = W1[i * 15 + j0];
            g_stage[2 * q + 1] = (j1 < 15) ? W1[i * 15 + j1] : 0.f;
        }
        for (int q = tid; q < 40; q += BTHR) {          // W2 pairs
            int p = q / 5, kk = q % 5;
            int j0 = 2 * p, j1 = j0 + 1;
            g_stage[80 + 2 * q]     = W2[j0 * 5 + kk];
            g_stage[80 + 2 * q + 1] = (j1 < 15) ? W2[j1 * 5 + kk] : 0.f;
        }
        if (tid >= 128 && tid < 133) g_stage[160 + tid - 128] = b2[tid - 128];
        if (tid >= 160 && tid < 210) g_stage[165 + tid - 160] = W3[tid - 160];
        if (tid >= 224 && tid < 234) g_stage[215 + tid - 224] = b3[tid - 224];
        if (tid >= 256 && tid < 326) g_stage[225 + tid - 256] = W4[tid - 256];
        if (tid >= 352 && tid < 359) g_stage[295 + tid - 352] = b4[tid - 352];
    }
    gsyncN(&g_arrive, BNBLK);

    // phase 1: histogram of rows
    for (int e = gi; e < N_EDGES; e += gsz) atomicAdd(&g_cnt[rows[e]], 1);
    gsyncN(&g_arrive, BNBLK);

    // phase 2: per-block chunk scan (Hillis-Steele)
    const int nn = bid * BNODE_CHUNK + tid;
    int cv = (tid < BNODE_CHUNK && nn < N_NODES) ? g_cnt[nn] : 0;
    sarr[tid] = cv;
    __syncthreads();
    for (int d = 1; d < BTHR; d <<= 1) {
        int v = (tid >= d) ? sarr[tid - d] : 0;
        __syncthreads();
        sarr[tid] += v;
        __syncthreads();
    }
    if (tid == BTHR - 1) g_part[bid] = sarr[BTHR - 1];
    gsyncN(&g_arrive, BNBLK);

    // phase 3: block 0 scans partials
    if (bid == 0) {
        if (tid < BNBLK) spart[tid] = g_part[tid];
        __syncthreads();
        if (tid == 0) {
            int run = 0;
            for (int i = 0; i < BNBLK; i++) { int t = spart[i]; spart[i] = run; run += t; }
        }
        __syncthreads();
        if (tid < BNBLK) g_part[tid] = spart[tid];
    }
    gsyncN(&g_arrive, BNBLK);

    // phase 4: exclusive cursors
    {
        int off = g_part[bid];
        if (tid < BNODE_CHUNK && nn < N_NODES) g_cur[nn] = off + sarr[tid] - cv;
    }
    gsyncN(&g_arrive, BNBLK);

    // phase 5: scatter edge order
    for (int e = gi; e < N_EDGES; e += gsz) {
        int p = atomicAdd(&g_cur[rows[e]], 1);
        g_eord[p] = e;
    }
    gsyncN(&g_arrive, BNBLK);

    // phase 6: permute + pre1 compute (fp16 pairs, 2x uint4) + segment metadata
    {
        const int lane = tid & 31;
        const int gw = bid * BWPB + (tid >> 5);
        const float4* ef4 = (const float4*)ef;
        const ull* w1a = (const ull*)sW1a;
        const ull* b1a = (const ull*)sB1a;
        for (int g = gw; g < NGROUPS; g += BNWARPS) {
            int i = g * 32 + lane;
            int e = g_eord[i];
            int r = rows[e];
            float4 f0 = ef4[e * 2];
            float4 f1 = ef4[e * 2 + 1];
            float in8[8] = {f0.x, f0.y, f0.z, f0.w, f1.x, f1.y, f1.z, f1.w};
            ull acc[8];
#pragma unroll
            for (int p = 0; p < 8; p++) acc[p] = b1a[p];
#pragma unroll
            for (int i8 = 0; i8 < 8; i8++) {
                ull x2 = pack2(in8[i8]);
#pragma unroll
                for (int p = 0; p < 8; p++)
                    acc[p] = fma2(x2, w1a[i8 * 8 + p], acc[p]);
            }
            __half2 hp[8];
#pragma unroll
            for (int p = 0; p < 8; p++) {
                float a, b;
                unpack2(acc[p], a, b);
                hp[p] = __floats2half2_rn(a, (p < 7) ? b : 0.f);
            }
            uint4 q0, q1;
            q0.x = *(unsigned*)&hp[0]; q0.y = *(unsigned*)&hp[1];
            q0.z = *(unsigned*)&hp[2]; q0.w = *(unsigned*)&hp[3];
            q1.x = *(unsigned*)&hp[4]; q1.y = *(unsigned*)&hp[5];
            q1.z = *(unsigned*)&hp[6]; q1.w = *(unsigned*)&hp[7];
            g_pre1h[i * 2]     = q0;
            g_pre1h[i * 2 + 1] = q1;
            g_sa[i] = make_int2(src[e], __float_as_int(avals[e]));
            int prev = __shfl_up_sync(FULLM, r, 1);
            bool head = (lane == 0) || (r != prev);
            unsigned hm = __ballot_sync(FULLM, head);
            unsigned below = hm & (FULLM >> (31 - lane));
            int segoff = lane - (31 - __clz(below));
            bool tail = (lane == 31) || ((hm >> (lane + 1)) & 1u);
            g_rowp[i] = r | (segoff << 18) | (tail ? (1 << 23) : 0);
        }
    }
}

// ===== persistent main kernel (296 x 768 = 48 warps/SM) =====
__global__ __launch_bounds__(MTHR, 2)
void gnn_main_k(const float* __restrict__ st0,
                const float* __restrict__ old0,
                float* __restrict__ out, int write_num) {
    const int tid = threadIdx.x;
    const int bid = blockIdx.x;
    const int lane = tid & 31;
    // transposed warp indexing: remainder groups spread across all blocks
    const int gw0 = (tid >> 5) * MNBLK + bid;

    const int myNode = bid * MNODE_CHUNK + tid;
    const bool owner = (tid < MNODE_CHUNK) && (myNode < N_NODES);
    float s[5], o[5];
    {
        int f = 0;
        if (owner) {
            float ss = 0.f;
#pragma unroll
            for (int i = 0; i < 5; i++) {
                s[i] = st0[myNode * 5 + i];
                o[i] = old0[myNode * 5 + i];
                float d = s[i] - o[i];
                ss += d * d;
            }
            __half2 p01 = __floats2half2_rn(s[0], s[1]);
            __half2 p23 = __floats2half2_rn(s[2], s[3]);
            __half2 p4  = __floats2half2_rn(s[4], 0.f);
            uint4 sv;
            sv.x = *(unsigned*)&p01; sv.y = *(unsigned*)&p23;
            sv.z = *(unsigned*)&p4;  sv.w = 0u;
            __stcg(&g_stateh[myNode], sv);
            __stcg(&g_acc4[myNode * 2], make_float4(0.f, 0.f, 0.f, 0.f));
            __stcg(((float*)&g_acc4[myNode * 2]) + 4, 0.f);
            if (sqrtf(ss + 1e-11f) > THRESH) f = 1;
        }
        int anyf = __syncthreads_or(f);
        if (tid == 0 && anyf) atomicOr(&g_flag_arr[0], 1);
    }
    gsyncN(&g_arrive2, MNBLK);

    const ull* w1s = (const ull*)cw.W1s;
    const ull* w2u = (const ull*)cw.W2u;

    int k = 0;
    for (int it = 0; it < MAX_ITER; ++it) {
        if (__ldcg(&g_flag_arr[it]) == 0) break;
        k++;

        // ===== edge phase: simple in-body loads, 48 warps hide latency =====
        for (int g = gw0; g < NGROUPS; g += MNWARPS) {
            int e = g * 32 + lane;
            // issue all loads up front (high MLP)
            int2 sa = __ldg(&g_sa[e]);
            int crp = __ldg(&g_rowp[e]);
            uint4 cp0 = __ldg(&g_pre1h[e * 2]);
            uint4 cp1 = __ldg(&g_pre1h[e * 2 + 1]);
            uint4 csv = __ldcg(&g_stateh[sa.x]);
            float cav = __int_as_float(sa.y);

            float2 p01 = __half22float2(*(__half2*)&csv.x);
            float2 p23 = __half22float2(*(__half2*)&csv.y);
            float2 p4  = __half22float2(*(__half2*)&csv.z);
            float sx0 = p01.x, sx1 = p01.y, sx2 = p23.x, sx3 = p23.y, sx4 = p4.x;

            ull z[5];
#pragma unroll
            for (int kk = 0; kk < 5; kk++) z[kk] = pack2f(cw.B2[kk], 0.f);

            // ---- half A: acc[0..3] from pr0 ----
            {
                const __half2* ph0 = (const __half2*)&cp0;
                ull acc[4];
#pragma unroll
                for (int p = 0; p < 4; p++) {
                    float2 f = __half22float2(ph0[p]);
                    acc[p] = pack2f(f.x, f.y);
                }
                {
                    ull x2 = pack2(sx0);
#pragma unroll
                    for (int p = 0; p < 4; p++) acc[p] = fma2(x2, w1s[p], acc[p]);
                }
                {
                    ull x2 = pack2(sx1);
#pragma unroll
                    for (int p = 0; p < 4; p++) acc[p] = fma2(x2, w1s[8 + p], acc[p]);
                }
                {
                    ull x2 = pack2(sx2);
#pragma unroll
                    for (int p = 0; p < 4; p++) acc[p] = fma2(x2, w1s[16 + p], acc[p]);
                }
                {
                    ull x2 = pack2(sx3);
#pragma unroll
                    for (int p = 0; p < 4; p++) acc[p] = fma2(x2, w1s[24 + p], acc[p]);
                }
                {
                    ull x2 = pack2(sx4);
#pragma unroll
                    for (int p = 0; p < 4; p++) acc[p] = fma2(x2, w1s[32 + p], acc[p]);
                }
#pragma unroll
                for (int p = 0; p < 4; p++) {
                    float a, b;
                    unpack2(acc[p], a, b);
                    ull hp = pack2f(tanha(a), tanha(b));
#pragma unroll
                    for (int kk = 0; kk < 5; kk++)
                        z[kk] = fma2(hp, w2u[p * 5 + kk], z[kk]);
                }
            }
            // ---- half B: acc[4..7] from pr1 ----
            {
                const __half2* ph1 = (const __half2*)&cp1;
                ull acc[4];
#pragma unroll
                for (int p = 0; p < 4; p++) {
                    float2 f = __half22float2(ph1[p]);
                    acc[p] = pack2f(f.x, f.y);
                }
                {
                    ull x2 = pack2(sx0);
#pragma unroll
                    for (int p = 0; p < 4; p++) acc[p] = fma2(x2, w1s[4 + p], acc[p]);
                }
                {
                    ull x2 = pack2(sx1);
#pragma unroll
                    for (int p = 0; p < 4; p++) acc[p] = fma2(x2, w1s[12 + p], acc[p]);
                }
                {
                    ull x2 = pack2(sx2);
#pragma unroll
                    for (int p = 0; p < 4; p++) acc[p] = fma2(x2, w1s[20 + p], acc[p]);
                }
                {
                    ull x2 = pack2(sx3);
#pragma unroll
                    for (int p = 0; p < 4; p++) acc[p] = fma2(x2, w1s[28 + p], acc[p]);
                }
                {
                    ull x2 = pack2(sx4);
#pragma unroll
                    for (int p = 0; p < 4; p++) acc[p] = fma2(x2, w1s[36 + p], acc[p]);
                }
#pragma unroll
                for (int p = 0; p < 4; p++) {
                    float a, b;
                    unpack2(acc[p], a, b);
                    ull hp = pack2f(tanha(a), tanha(b));   // p==3 hi pad: weight 0
#pragma unroll
                    for (int kk = 0; kk < 5; kk++)
                        z[kk] = fma2(hp, w2u[(4 + p) * 5 + kk], z[kk]);
                }
            }

            // layer-2 tanh (1 MUFU each) + arc weight
            float v0, v1, v2, v3, v4;
            {
                float lo, hi;
                unpack2(z[0], lo, hi); v0 = tanha(lo + hi) * cav;
                unpack2(z[1], lo, hi); v1 = tanha(lo + hi) * cav;
                unpack2(z[2], lo, hi); v2 = tanha(lo + hi) * cav;
                unpack2(z[3], lo, hi); v3 = tanha(lo + hi) * cav;
                unpack2(z[4], lo, hi); v4 = tanha(lo + hi) * cav;
            }

            // segmented inclusive scan over sorted rows (packed)
            int segoff = (crp >> 18) & 31;
            ull v01 = pack2f(v0, v1);
            ull v23 = pack2f(v2, v3);
#pragma unroll
            for (int d = 1; d < 32; d <<= 1) {
                ull t01 = __shfl_up_sync(FULLM, v01, d);
                ull t23 = __shfl_up_sync(FULLM, v23, d);
                float t4 = __shfl_up_sync(FULLM, v4, d);
                if (segoff >= d) { v01 = add2(v01, t01); v23 = add2(v23, t23); v4 += t4; }
            }
            if (crp & (1 << 23)) {
                int crow = crp & 0x3FFFF;
                float a0, a1, a2, a3;
                unpack2(v01, a0, a1);
                unpack2(v23, a2, a3);
                float* ap = (float*)&g_acc4[crow * 2];
                asm volatile("red.global.add.v4.f32 [%0], {%1,%2,%3,%4};"
                             :: "l"(ap), "f"(a0), "f"(a1), "f"(a2), "f"(a3) : "memory");
                asm volatile("red.global.add.f32 [%0], %1;"
                             :: "l"(ap + 4), "f"(v4) : "memory");
            }
        }
        gsyncN(&g_arrive2, MNBLK);

        // ===== node phase =====
        {
            int f = 0;
            if (owner) {
                float4 a = __ldcg(&g_acc4[myNode * 2]);
                float a4 = __ldcg(((const float*)&g_acc4[myNode * 2]) + 4);
                __stcg(&g_acc4[myNode * 2], make_float4(0.f, 0.f, 0.f, 0.f));
                __stcg(((float*)&g_acc4[myNode * 2]) + 4, 0.f);
                o[0] = s[0]; o[1] = s[1]; o[2] = s[2]; o[3] = s[3]; o[4] = s[4];
                s[0] = a.x; s[1] = a.y; s[2] = a.z; s[3] = a.w; s[4] = a4;
                __half2 p01 = __floats2half2_rn(s[0], s[1]);
                __half2 p23 = __floats2half2_rn(s[2], s[3]);
                __half2 p4  = __floats2half2_rn(s[4], 0.f);
                uint4 svw;
                svw.x = *(unsigned*)&p01; svw.y = *(unsigned*)&p23;
                svw.z = *(unsigned*)&p4;  svw.w = 0u;
                __stcg(&g_stateh[myNode], svw);
                float ss = 0.f;
#pragma unroll
                for (int i = 0; i < 5; i++) { float d = s[i] - o[i]; ss += d * d; }
                if (sqrtf(ss + 1e-11f) > THRESH) f = 1;
            }
            int anyf = __syncthreads_or(f);
            if (tid == 0 && anyf) atomicOr(&g_flag_arr[it + 1], 1);
        }
        gsyncN(&g_arrive2, MNBLK);
    }

    // ===== readout (precise) =====
    if (owner) {
        float h[10];
#pragma unroll
        for (int j = 0; j < 10; j++) {
            float a = cw.B3[j];
#pragma unroll
            for (int i = 0; i < 5; i++) a += s[i] * cw.W3[i * 10 + j];
            h[j] = tanhf(a);
        }
        float l[7];
        float m = -1e30f;
#pragma unroll
        for (int c = 0; c < 7; c++) {
            float a = cw.B4[c];
#pragma unroll
            for (int j = 0; j < 10; j++) a += h[j] * cw.W4[j * 7 + c];
            l[c] = a;
            m = fmaxf(m, a);
        }
        float sum = 0.f;
#pragma unroll
        for (int c = 0; c < 7; c++) { float ev = expf(l[c] - m); l[c] = ev; sum += ev; }
        float inv = 1.0f / sum;
#pragma unroll
        for (int c = 0; c < 7; c++) out[(size_t)myNode * 7 + c] = l[c] * inv;
    }
    if (bid == 0 && tid == 0 && write_num) out[(size_t)N_NODES * 7] = (float)k;
}

extern "C" void kernel_launch(void* const* d_in, const int* in_sizes, int n_in,
                              void* d_out, int out_size) {
    const float* edge_feat = (const float*)d_in[0];
    const int*   edge_src  = (const int*)d_in[1];
    const int*   arc_rows  = (const int*)d_in[2];
    const float* arc_vals  = (const float*)d_in[3];
    const float* st0       = (const float*)d_in[4];
    const float* old0      = (const float*)d_in[5];
    const float* W1        = (const float*)d_in[6];
    const float* b1        = (const float*)d_in[7];
    const float* W2        = (const float*)d_in[8];
    const float* b2        = (const float*)d_in[9];
    const float* W3        = (const float*)d_in[10];
    const float* b3        = (const float*)d_in[11];
    const float* W4        = (const float*)d_in[12];
    const float* b4        = (const float*)d_in[13];
    float* out = (float*)d_out;

    build_k<<<BNBLK, BTHR>>>(edge_feat, edge_src, arc_rows, arc_vals,
                             W1, b1, W2, b2, W3, b3, W4, b4);

    void *pCW, *pStage;
    cudaGetSymbolAddress(&pCW, cw);
    cudaGetSymbolAddress(&pStage, g_stage);
    cudaMemcpyAsync(pCW, pStage, sizeof(CW), cudaMemcpyDeviceToDevice, 0);

    gnn_main_k<<<MNBLK, MTHR>>>(st0, old0, out, (out_size > N_NODES * 7) ? 1 : 0);
}

// round 15
// speedup vs baseline: 1.0779x; 1.0779x over previous
#include <cuda_runtime.h>
#include <cuda_fp16.h>
#include <math.h>

#define N_NODES 100000
#define N_EDGES 1600000
#define MAX_ITER 50
#define THRESH 0.01f

#define NBLK 148
#define NTHR 1024
#define WPB (NTHR / 32)                     // 32 warps/block
#define NWARPS (NBLK * WPB)                 // 4736
#define NGROUPS (N_EDGES / 32)              // 50000 exact
#define NODE_CHUNK ((N_NODES + NBLK - 1) / NBLK)   // 676
#define FULLM 0xffffffffu

typedef unsigned long long ull;

// all weights in one constant block (single D2D memcpy)
struct CW {
    float2 W1s[40];   // W1 rows 8..12, j-paired: [i=5][jp=8]
    float2 W2u[40];   // [p=8][k=5]: (W2[2p][k], W2[2p+1][k] or 0)
    float  B2[5];
    float  W3[50], B3[10], W4[70], B4[7];
};
__constant__ CW cw;

// ---- static device scratch ----
__device__ unsigned g_arrive;               // zero-init, monotonic forever
__device__ uint4  g_stateh[N_NODES];        // state as fp16 (5 used of 8)
__device__ float4 g_acc4[N_NODES * 2];      // fp32 accumulator, stride 8
__device__ int    g_flag_arr[MAX_ITER + 2];
__device__ int    g_cnt[N_NODES];
__device__ int    g_cur[N_NODES];
__device__ int    g_part[NBLK];
__device__ uint4  g_pre1h[N_EDGES * 2];     // (b1 + ef@W1[0:8]) fp16 j-pairs, 32B/edge
__device__ int4   g_meta4[N_EDGES];         // {src, av bits, row, row|segoff<<18|tail<<23}
__device__ float  g_stage[304];

// single-MUFU tanh (abs err ~5e-4)
__device__ __forceinline__ float tanha(float x) {
    float r; asm("tanh.approx.f32 %0, %1;" : "=f"(r) : "f"(x)); return r;
}
__device__ __forceinline__ ull pack2(float x) {
    ull r; asm("mov.b64 %0, {%1, %1};" : "=l"(r) : "f"(x)); return r;
}
__device__ __forceinline__ ull pack2f(float lo, float hi) {
    ull r; asm("mov.b64 %0, {%1, %2};" : "=l"(r) : "f"(lo), "f"(hi)); return r;
}
__device__ __forceinline__ ull fma2(ull a, ull b, ull c) {
    ull r; asm("fma.rn.f32x2 %0, %1, %2, %3;" : "=l"(r) : "l"(a), "l"(b), "l"(c)); return r;
}
__device__ __forceinline__ ull add2(ull a, ull b) {
    ull r; asm("add.rn.f32x2 %0, %1, %2;" : "=l"(r) : "l"(a), "l"(b)); return r;
}
__device__ __forceinline__ void unpack2(ull v, float& lo, float& hi) {
    asm("mov.b64 {%0, %1}, %2;" : "=f"(lo), "=f"(hi) : "l"(v));
}

// grid barrier: release-arrive + acquire-spin; monotonic counter, no reset
__device__ __forceinline__ void gsync() {
    __syncthreads();
    if (threadIdx.x == 0) {
        unsigned old;
        asm volatile("atom.add.release.gpu.global.u32 %0, [%1], 1;"
                     : "=r"(old) : "l"(&g_arrive) : "memory");
        unsigned tgt = (old / NBLK + 1u) * NBLK;
        unsigned cur;
        do {
            asm volatile("ld.acquire.gpu.global.u32 %0, [%1];"
                         : "=r"(cur) : "l"(&g_arrive) : "memory");
        } while (cur < tgt);
    }
    __syncthreads();
}

// ===== one persistent build kernel =====
__global__ __launch_bounds__(NTHR, 1)
void build_k(const float* __restrict__ ef, const int* __restrict__ src,
             const int* __restrict__ rows, const float* __restrict__ avals,
             const float* __restrict__ W1, const float* __restrict__ b1,
             const float* __restrict__ W2, const float* __restrict__ b2,
             const float* __restrict__ W3, const float* __restrict__ b3,
             const float* __restrict__ W4, const float* __restrict__ b4) {
    __shared__ int sarr[NTHR];
    __shared__ int spart[NBLK];
    __shared__ float2 sW1a[64];   // W1 rows 0..7, j-paired [i8][jp]
    __shared__ float2 sB1a[8];    // b1 j-paired
    const int tid = threadIdx.x, bid = blockIdx.x;
    const int gsz = NBLK * NTHR;
    const int gi = bid * NTHR + tid;

    // phase 0: zero counters/flags, stage smem W1a/b1 (all blocks), constants (block 0)
    for (int n = gi; n < N_NODES; n += gsz) g_cnt[n] = 0;
    if (gi < MAX_ITER + 2) g_flag_arr[gi] = 0;
    if (tid < 64) {
        int i8 = tid >> 3, jp = tid & 7;
        int j0 = jp * 2, j1 = j0 + 1;
        sW1a[tid] = make_float2(W1[i8 * 15 + j0],
                                (j1 < 15) ? W1[i8 * 15 + j1] : 0.f);
    } else if (tid < 72) {
        int jp = tid - 64;
        int j0 = jp * 2, j1 = j0 + 1;
        sB1a[jp] = make_float2(b1[j0], (j1 < 15) ? b1[j1] : 0.f);
    }
    if (bid == 0) {
        for (int q = tid; q < 40; q += NTHR) {          // W1 rows 8..12
            int i = 8 + (q >> 3), jp = q & 7;
            int j0 = jp * 2, j1 = j0 + 1;
            g_stage[2 * q]     = W1[i * 15 + j0];
            g_stage[2 * q + 1] = (j1 < 15) ? W1[i * 15 + j1] : 0.f;
        }
        for (int q = tid; q < 40; q += NTHR) {          // W2 pairs
            int p = q / 5, kk = q % 5;
            int j0 = 2 * p, j1 = j0 + 1;
            g_stage[80 + 2 * q]     = W2[j0 * 5 + kk];
            g_stage[80 + 2 * q + 1] = (j1 < 15) ? W2[j1 * 5 + kk] : 0.f;
        }
        if (tid >= 128 && tid < 133) g_stage[160 + tid - 128] = b2[tid - 128];
        if (tid >= 160 && tid < 210) g_stage[165 + tid - 160] = W3[tid - 160];
        if (tid >= 224 && tid < 234) g_stage[215 + tid - 224] = b3[tid - 224];
        if (tid >= 256 && tid < 326) g_stage[225 + tid - 256] = W4[tid - 256];
        if (tid >= 352 && tid < 359) g_stage[295 + tid - 352] = b4[tid - 352];
    }
    gsync();

    // phase 1: histogram of rows
    for (int e = gi; e < N_EDGES; e += gsz) atomicAdd(&g_cnt[rows[e]], 1);
    gsync();

    // phase 2: per-block chunk scan (Hillis-Steele)
    const int nn = bid * NODE_CHUNK + tid;
    int cv = (tid < NODE_CHUNK && nn < N_NODES) ? g_cnt[nn] : 0;
    sarr[tid] = cv;
    __syncthreads();
    for (int d = 1; d < NTHR; d <<= 1) {
        int v = (tid >= d) ? sarr[tid - d] : 0;
        __syncthreads();
        sarr[tid] += v;
        __syncthreads();
    }
    if (tid == NTHR - 1) g_part[bid] = sarr[NTHR - 1];
    gsync();

    // phase 3: block 0 scans partials
    if (bid == 0) {
        if (tid < NBLK) spart[tid] = g_part[tid];
        __syncthreads();
        if (tid == 0) {
            int run = 0;
            for (int i = 0; i < NBLK; i++) { int t = spart[i]; spart[i] = run; run += t; }
        }
        __syncthreads();
        if (tid < NBLK) g_part[tid] = spart[tid];
    }
    gsync();

    // phase 4: exclusive cursors
    {
        int off = g_part[bid];
        if (tid < NODE_CHUNK && nn < N_NODES) g_cur[nn] = off + sarr[tid] - cv;
    }
    gsync();

    // phase 5: FUSED scatter: coalesced reads of edge data, compute pre1,
    // scatter-write pre1h + meta to the row-sorted position (no eord array)
    {
        const float4* ef4 = (const float4*)ef;
        const ull* w1a = (const ull*)sW1a;
        const ull* b1a = (const ull*)sB1a;
        for (int e = gi; e < N_EDGES; e += gsz) {
            int r = rows[e];
            float4 f0 = ef4[e * 2];
            float4 f1 = ef4[e * 2 + 1];
            int p = atomicAdd(&g_cur[r], 1);
            float in8[8] = {f0.x, f0.y, f0.z, f0.w, f1.x, f1.y, f1.z, f1.w};
            ull acc[8];
#pragma unroll
            for (int q = 0; q < 8; q++) acc[q] = b1a[q];
#pragma unroll
            for (int i8 = 0; i8 < 8; i8++) {
                ull x2 = pack2(in8[i8]);
#pragma unroll
                for (int q = 0; q < 8; q++)
                    acc[q] = fma2(x2, w1a[i8 * 8 + q], acc[q]);
            }
            __half2 hp[8];
#pragma unroll
            for (int q = 0; q < 8; q++) {
                float a, b;
                unpack2(acc[q], a, b);
                hp[q] = __floats2half2_rn(a, (q < 7) ? b : 0.f);
            }
            uint4 q0, q1;
            q0.x = *(unsigned*)&hp[0]; q0.y = *(unsigned*)&hp[1];
            q0.z = *(unsigned*)&hp[2]; q0.w = *(unsigned*)&hp[3];
            q1.x = *(unsigned*)&hp[4]; q1.y = *(unsigned*)&hp[5];
            q1.z = *(unsigned*)&hp[6]; q1.w = *(unsigned*)&hp[7];
            g_pre1h[(size_t)p * 2]     = q0;
            g_pre1h[(size_t)p * 2 + 1] = q1;
            g_meta4[p] = make_int4(src[e], __float_as_int(avals[e]), r, 0);
        }
    }
    gsync();

    // phase 6: segment metadata pass (coalesced over sorted order)
    {
        const int lane = tid & 31;
        const int gw = bid * WPB + (tid >> 5);
        for (int g = gw; g < NGROUPS; g += NWARPS) {
            int i = g * 32 + lane;
            int r = g_meta4[i].z;
            int prev = __shfl_up_sync(FULLM, r, 1);
            bool head = (lane == 0) || (r != prev);
            unsigned hm = __ballot_sync(FULLM, head);
            unsigned below = hm & (FULLM >> (31 - lane));
            int segoff = lane - (31 - __clz(below));
            bool tail = (lane == 31) || ((hm >> (lane + 1)) & 1u);
            g_meta4[i].w = r | (segoff << 18) | (tail ? (1 << 23) : 0);
        }
    }
}

// ===== persistent main kernel (R11 structure, merged int4 metadata) =====
__global__ __launch_bounds__(NTHR, 1)
void gnn_main_k(const float* __restrict__ st0,
                const float* __restrict__ old0,
                float* __restrict__ out, int write_num) {
    const int tid = threadIdx.x;
    const int bid = blockIdx.x;
    const int lane = tid & 31;
    const int gw = bid * WPB + (tid >> 5);

    const int myNode = bid * NODE_CHUNK + tid;
    const bool owner = (tid < NODE_CHUNK) && (myNode < N_NODES);
    float s[5], o[5];
    {
        int f = 0;
        if (owner) {
            float ss = 0.f;
#pragma unroll
            for (int i = 0; i < 5; i++) {
                s[i] = st0[myNode * 5 + i];
                o[i] = old0[myNode * 5 + i];
                float d = s[i] - o[i];
                ss += d * d;
            }
            __half2 p01 = __floats2half2_rn(s[0], s[1]);
            __half2 p23 = __floats2half2_rn(s[2], s[3]);
            __half2 p4  = __floats2half2_rn(s[4], 0.f);
            uint4 sv;
            sv.x = *(unsigned*)&p01; sv.y = *(unsigned*)&p23;
            sv.z = *(unsigned*)&p4;  sv.w = 0u;
            __stcg(&g_stateh[myNode], sv);
            __stcg(&g_acc4[myNode * 2], make_float4(0.f, 0.f, 0.f, 0.f));
            __stcg(((float*)&g_acc4[myNode * 2]) + 4, 0.f);
            if (sqrtf(ss + 1e-11f) > THRESH) f = 1;
        }
        int anyf = __syncthreads_or(f);
        if (tid == 0 && anyf) atomicOr(&g_flag_arr[0], 1);
    }
    gsync();

    const ull* w1s = (const ull*)cw.W1s;
    const ull* w2u = (const ull*)cw.W2u;

    int k = 0;
    for (int it = 0; it < MAX_ITER; ++it) {
        if (__ldcg(&g_flag_arr[it]) == 0) break;
        k++;

        // ===== edge phase: software-pipelined (full prefetch) =====
        int g = gw;
        int4 mv = make_int4(0, 0, 0, 0);
        uint4 sv = make_uint4(0, 0, 0, 0);
        uint4 pr0 = make_uint4(0, 0, 0, 0);
        uint4 pr1 = make_uint4(0, 0, 0, 0);
        if (g < NGROUPS) {
            int e = g * 32 + lane;
            mv = __ldg(&g_meta4[e]);
            pr0 = __ldg(&g_pre1h[e * 2]);
            pr1 = __ldg(&g_pre1h[e * 2 + 1]);
            sv = __ldcg(&g_stateh[mv.x]);
        }
        while (g < NGROUPS) {
            int gn = g + NWARPS;

            uint4 cp0 = pr0, cp1 = pr1;
            uint4 csv = sv;
            int crp = mv.w;
            float cav = __int_as_float(mv.y);
            if (gn < NGROUPS) {
                int en = gn * 32 + lane;
                mv = __ldg(&g_meta4[en]);
                pr0 = __ldg(&g_pre1h[en * 2]);
                pr1 = __ldg(&g_pre1h[en * 2 + 1]);
                sv = __ldcg(&g_stateh[mv.x]);
            }

            float2 p01 = __half22float2(*(__half2*)&csv.x);
            float2 p23 = __half22float2(*(__half2*)&csv.y);
            float2 p4  = __half22float2(*(__half2*)&csv.z);
            float sx[5] = {p01.x, p01.y, p23.x, p23.y, p4.x};

            // layer 1: acc = pre1 + state @ W1[8:13]
            const __half2* ph0 = (const __half2*)&cp0;
            const __half2* ph1 = (const __half2*)&cp1;
            ull acc[8];
#pragma unroll
            for (int p = 0; p < 4; p++) {
                float2 f = __half22float2(ph0[p]);
                acc[p] = pack2f(f.x, f.y);
            }
#pragma unroll
            for (int p = 0; p < 4; p++) {
                float2 f = __half22float2(ph1[p]);
                acc[4 + p] = pack2f(f.x, f.y);
            }
#pragma unroll
            for (int i = 0; i < 5; i++) {
                ull x2 = pack2(sx[i]);
#pragma unroll
                for (int p = 0; p < 8; p++)
                    acc[p] = fma2(x2, w1s[i * 8 + p], acc[p]);
            }

            // tanh (1 MUFU each) + layer 2
            ull z[5];
#pragma unroll
            for (int kk = 0; kk < 5; kk++) z[kk] = pack2f(cw.B2[kk], 0.f);
#pragma unroll
            for (int p = 0; p < 8; p++) {
                float a, b;
                unpack2(acc[p], a, b);
                float ta = tanha(a);
                float tb = tanha(b);   // p==7 hi is 0 -> tanh(0)=0, weight 0
                ull hp = pack2f(ta, tb);
#pragma unroll
                for (int kk = 0; kk < 5; kk++)
                    z[kk] = fma2(hp, w2u[p * 5 + kk], z[kk]);
            }
            // layer-2 tanh (1 MUFU each) + arc weight
            float v0, v1, v2, v3, v4;
            {
                float lo, hi;
                unpack2(z[0], lo, hi); v0 = tanha(lo + hi) * cav;
                unpack2(z[1], lo, hi); v1 = tanha(lo + hi) * cav;
                unpack2(z[2], lo, hi); v2 = tanha(lo + hi) * cav;
                unpack2(z[3], lo, hi); v3 = tanha(lo + hi) * cav;
                unpack2(z[4], lo, hi); v4 = tanha(lo + hi) * cav;
            }

            // segmented inclusive scan over sorted rows (packed)
            int segoff = (crp >> 18) & 31;
            ull v01 = pack2f(v0, v1);
            ull v23 = pack2f(v2, v3);
#pragma unroll
            for (int d = 1; d < 32; d <<= 1) {
                ull t01 = __shfl_up_sync(FULLM, v01, d);
                ull t23 = __shfl_up_sync(FULLM, v23, d);
                float t4 = __shfl_up_sync(FULLM, v4, d);
                if (segoff >= d) { v01 = add2(v01, t01); v23 = add2(v23, t23); v4 += t4; }
            }
            if (crp & (1 << 23)) {
                int crow = crp & 0x3FFFF;
                float a0, a1, a2, a3;
                unpack2(v01, a0, a1);
                unpack2(v23, a2, a3);
                float* ap = (float*)&g_acc4[crow * 2];
                asm volatile("red.global.add.v4.f32 [%0], {%1,%2,%3,%4};"
                             :: "l"(ap), "f"(a0), "f"(a1), "f"(a2), "f"(a3) : "memory");
                asm volatile("red.global.add.f32 [%0], %1;"
                             :: "l"(ap + 4), "f"(v4) : "memory");
            }
            g = gn;
        }
        gsync();

        // ===== node phase =====
        {
            int f = 0;
            if (owner) {
                float4 a = __ldcg(&g_acc4[myNode * 2]);
                float a4 = __ldcg(((const float*)&g_acc4[myNode * 2]) + 4);
                __stcg(&g_acc4[myNode * 2], make_float4(0.f, 0.f, 0.f, 0.f));
                __stcg(((float*)&g_acc4[myNode * 2]) + 4, 0.f);
                o[0] = s[0]; o[1] = s[1]; o[2] = s[2]; o[3] = s[3]; o[4] = s[4];
                s[0] = a.x; s[1] = a.y; s[2] = a.z; s[3] = a.w; s[4] = a4;
                __half2 p01 = __floats2half2_rn(s[0], s[1]);
                __half2 p23 = __floats2half2_rn(s[2], s[3]);
                __half2 p4  = __floats2half2_rn(s[4], 0.f);
                uint4 svw;
                svw.x = *(unsigned*)&p01; svw.y = *(unsigned*)&p23;
                svw.z = *(unsigned*)&p4;  svw.w = 0u;
                __stcg(&g_stateh[myNode], svw);
                float ss = 0.f;
#pragma unroll
                for (int i = 0; i < 5; i++) { float d = s[i] - o[i]; ss += d * d; }
                if (sqrtf(ss + 1e-11f) > THRESH) f = 1;
            }
            int anyf = __syncthreads_or(f);
            if (tid == 0 && anyf) atomicOr(&g_flag_arr[it + 1], 1);
        }
        gsync();
    }

    // ===== readout (precise) =====
    if (owner) {
        float h[10];
#pragma unroll
        for (int j = 0; j < 10; j++) {
            float a = cw.B3[j];
#pragma unroll
            for (int i = 0; i < 5; i++) a += s[i] * cw.W3[i * 10 + j];
            h[j] = tanhf(a);
        }
        float l[7];
        float m = -1e30f;
#pragma unroll
        for (int c = 0; c < 7; c++) {
            float a = cw.B4[c];
#pragma unroll
            for (int j = 0; j < 10; j++) a += h[j] * cw.W4[j * 7 + c];
            l[c] = a;
            m = fmaxf(m, a);
        }
        float sum = 0.f;
#pragma unroll
        for (int c = 0; c < 7; c++) { float ev = expf(l[c] - m); l[c] = ev; sum += ev; }
        float inv = 1.0f / sum;
#pragma unroll
        for (int c = 0; c < 7; c++) out[(size_t)myNode * 7 + c] = l[c] * inv;
    }
    if (bid == 0 && tid == 0 && write_num) out[(size_t)N_NODES * 7] = (float)k;
}

extern "C" void kernel_launch(void* const* d_in, const int* in_sizes, int n_in,
                              void* d_out, int out_size) {
    const float* edge_feat = (const float*)d_in[0];
    const int*   edge_src  = (const int*)d_in[1];
    const int*   arc_rows  = (const int*)d_in[2];
    const float* arc_vals  = (const float*)d_in[3];
    const float* st0       = (const float*)d_in[4];
    const float* old0      = (const float*)d_in[5];
    const float* W1        = (const float*)d_in[6];
    const float* b1        = (const float*)d_in[7];
    const float* W2        = (const float*)d_in[8];
    const float* b2        = (const float*)d_in[9];
    const float* W3        = (const float*)d_in[10];
    const float* b3        = (const float*)d_in[11];
    const float* W4        = (const float*)d_in[12];
    const float* b4        = (const float*)d_in[13];
    float* out = (float*)d_out;

    build_k<<<NBLK, NTHR>>>(edge_feat, edge_src, arc_rows, arc_vals,
                            W1, b1, W2, b2, W3, b3, W4, b4);

    void *pCW, *pStage;
    cudaGetSymbolAddress(&pCW, cw);
    cudaGetSymbolAddress(&pStage, g_stage);
    cudaMemcpyAsync(pCW, pStage, sizeof(CW), cudaMemcpyDeviceToDevice, 0);

    gnn_main_k<<<NBLK, NTHR>>>(st0, old0, out, (out_size > N_NODES * 7) ? 1 : 0);
}

// round 16
// speedup vs baseline: 1.1766x; 1.0916x over previous
#include <cuda_runtime.h>
#include <cuda_fp16.h>
#include <math.h>

#define N_NODES 100000
#define N_EDGES 1600000
#define MAX_ITER 50
#define THRESH 0.01f

#define NBLK 148
#define NTHR 1024
#define WPB (NTHR / 32)                     // 32 warps/block
#define NWARPS (NBLK * WPB)                 // 4736
#define NGROUPS (N_EDGES / 32)              // 50000 exact
#define NODE_CHUNK ((N_NODES + NBLK - 1) / NBLK)   // 676
#define FULLM 0xffffffffu

typedef unsigned long long ull;

// all weights in one constant block (single D2D memcpy)
struct CW {
    float2 W1s[40];   // W1 rows 8..12, j-paired: [i=5][jp=8]
    float2 W2u[40];   // [p=8][k=5]: (W2[2p][k], W2[2p+1][k] or 0)
    float  B2[5];
    float  W3[50], B3[10], W4[70], B4[7];
};
__constant__ CW cw;

// ---- static device scratch ----
__device__ unsigned g_arrive;               // zero-init, monotonic forever
__device__ uint4  g_stateh[N_NODES];        // state as fp16 (5 used of 8)
__device__ int    g_flag_arr[MAX_ITER + 2];
__device__ int    g_cnt[N_NODES];
__device__ int    g_cur[N_NODES];
__device__ int    g_part[NBLK + 1];         // per-block edge range boundaries
__device__ int    g_eord[N_EDGES];
__device__ uint4  g_pre1h[N_EDGES * 2];     // (b1 + ef@W1[0:8]) fp16 j-pairs, 32B/edge
__device__ int2   g_sa[N_EDGES];            // {src, av bits}
__device__ int    g_rowp[N_EDGES];          // localrow | segoff<<18 | tail<<23
__device__ float  g_stage[304];

// single-MUFU tanh (abs err ~5e-4)
__device__ __forceinline__ float tanha(float x) {
    float r; asm("tanh.approx.f32 %0, %1;" : "=f"(r) : "f"(x)); return r;
}
__device__ __forceinline__ ull pack2(float x) {
    ull r; asm("mov.b64 %0, {%1, %1};" : "=l"(r) : "f"(x)); return r;
}
__device__ __forceinline__ ull pack2f(float lo, float hi) {
    ull r; asm("mov.b64 %0, {%1, %2};" : "=l"(r) : "f"(lo), "f"(hi)); return r;
}
__device__ __forceinline__ ull fma2(ull a, ull b, ull c) {
    ull r; asm("fma.rn.f32x2 %0, %1, %2, %3;" : "=l"(r) : "l"(a), "l"(b), "l"(c)); return r;
}
__device__ __forceinline__ ull add2(ull a, ull b) {
    ull r; asm("add.rn.f32x2 %0, %1, %2;" : "=l"(r) : "l"(a), "l"(b)); return r;
}
__device__ __forceinline__ void unpack2(ull v, float& lo, float& hi) {
    asm("mov.b64 {%0, %1}, %2;" : "=f"(lo), "=f"(hi) : "l"(v));
}

// grid barrier: release-arrive + acquire-spin; monotonic counter, no reset
__device__ __forceinline__ void gsync() {
    __syncthreads();
    if (threadIdx.x == 0) {
        unsigned old;
        asm volatile("atom.add.release.gpu.global.u32 %0, [%1], 1;"
                     : "=r"(old) : "l"(&g_arrive) : "memory");
        unsigned tgt = (old / NBLK + 1u) * NBLK;
        unsigned cur;
        do {
            asm volatile("ld.acquire.gpu.global.u32 %0, [%1];"
                         : "=r"(cur) : "l"(&g_arrive) : "memory");
        } while (cur < tgt);
    }
    __syncthreads();
}

// ===== one persistent build kernel =====
__global__ __launch_bounds__(NTHR, 1)
void build_k(const float* __restrict__ ef, const int* __restrict__ src,
             const int* __restrict__ rows, const float* __restrict__ avals,
             const float* __restrict__ W1, const float* __restrict__ b1,
             const float* __restrict__ W2, const float* __restrict__ b2,
             const float* __restrict__ W3, const float* __restrict__ b3,
             const float* __restrict__ W4, const float* __restrict__ b4) {
    __shared__ int sarr[NTHR];
    __shared__ int spart[NBLK];
    __shared__ float2 sW1a[64];   // W1 rows 0..7, j-paired [i8][jp]
    __shared__ float2 sB1a[8];    // b1 j-paired
    const int tid = threadIdx.x, bid = blockIdx.x;
    const int gsz = NBLK * NTHR;
    const int gi = bid * NTHR + tid;

    // phase 0: zero counters/flags, stage smem W1a/b1, stage constants
    for (int n = gi; n < N_NODES; n += gsz) g_cnt[n] = 0;
    if (gi < MAX_ITER + 2) g_flag_arr[gi] = 0;
    if (tid < 64) {
        int i8 = tid >> 3, jp = tid & 7;
        int j0 = jp * 2, j1 = j0 + 1;
        sW1a[tid] = make_float2(W1[i8 * 15 + j0],
                                (j1 < 15) ? W1[i8 * 15 + j1] : 0.f);
    } else if (tid < 72) {
        int jp = tid - 64;
        int j0 = jp * 2, j1 = j0 + 1;
        sB1a[jp] = make_float2(b1[j0], (j1 < 15) ? b1[j1] : 0.f);
    }
    if (bid == 0) {
        for (int q = tid; q < 40; q += NTHR) {          // W1 rows 8..12
            int i = 8 + (q >> 3), jp = q & 7;
            int j0 = jp * 2, j1 = j0 + 1;
            g_stage[2 * q]     = W1[i * 15 + j0];
            g_stage[2 * q + 1] = (j1 < 15) ? W1[i * 15 + j1] : 0.f;
        }
        for (int q = tid; q < 40; q += NTHR) {          // W2 pairs
            int p = q / 5, kk = q % 5;
            int j0 = 2 * p, j1 = j0 + 1;
            g_stage[80 + 2 * q]     = W2[j0 * 5 + kk];
            g_stage[80 + 2 * q + 1] = (j1 < 15) ? W2[j1 * 5 + kk] : 0.f;
        }
        if (tid >= 128 && tid < 133) g_stage[160 + tid - 128] = b2[tid - 128];
        if (tid >= 160 && tid < 210) g_stage[165 + tid - 160] = W3[tid - 160];
        if (tid >= 224 && tid < 234) g_stage[215 + tid - 224] = b3[tid - 224];
        if (tid >= 256 && tid < 326) g_stage[225 + tid - 256] = W4[tid - 256];
        if (tid >= 352 && tid < 359) g_stage[295 + tid - 352] = b4[tid - 352];
    }
    gsync();

    // phase 1: histogram of rows
    for (int e = gi; e < N_EDGES; e += gsz) atomicAdd(&g_cnt[rows[e]], 1);
    gsync();

    // phase 2: per-block chunk scan (Hillis-Steele)
    const int nn = bid * NODE_CHUNK + tid;
    int cv = (tid < NODE_CHUNK && nn < N_NODES) ? g_cnt[nn] : 0;
    sarr[tid] = cv;
    __syncthreads();
    for (int d = 1; d < NTHR; d <<= 1) {
        int v = (tid >= d) ? sarr[tid - d] : 0;
        __syncthreads();
        sarr[tid] += v;
        __syncthreads();
    }
    if (tid == NTHR - 1) g_part[bid] = sarr[NTHR - 1];
    gsync();

    // phase 3: block 0 scans partials; exclusive prefix = per-block edge start
    if (bid == 0) {
        if (tid < NBLK) spart[tid] = g_part[tid];
        __syncthreads();
        if (tid == 0) {
            int run = 0;
            for (int i = 0; i < NBLK; i++) { int t = spart[i]; spart[i] = run; run += t; }
            g_part[NBLK] = N_EDGES;
        }
        __syncthreads();
        if (tid < NBLK) g_part[tid] = spart[tid];
    }
    gsync();

    // phase 4: exclusive cursors
    {
        int off = g_part[bid];
        if (tid < NODE_CHUNK && nn < N_NODES) g_cur[nn] = off + sarr[tid] - cv;
    }
    gsync();

    // phase 5: scatter edge order
    for (int e = gi; e < N_EDGES; e += gsz) {
        int p = atomicAdd(&g_cur[rows[e]], 1);
        g_eord[p] = e;
    }
    gsync();

    // phase 6: permute + pre1 compute (fp16 pairs); rowp = plain row for now
    {
        const int lane = tid & 31;
        const int gw = bid * WPB + (tid >> 5);
        const float4* ef4 = (const float4*)ef;
        const ull* w1a = (const ull*)sW1a;
        const ull* b1a = (const ull*)sB1a;
        for (int g = gw; g < NGROUPS; g += NWARPS) {
            int i = g * 32 + lane;
            int e = g_eord[i];
            float4 f0 = ef4[e * 2];
            float4 f1 = ef4[e * 2 + 1];
            float in8[8] = {f0.x, f0.y, f0.z, f0.w, f1.x, f1.y, f1.z, f1.w};
            ull acc[8];
#pragma unroll
            for (int p = 0; p < 8; p++) acc[p] = b1a[p];
#pragma unroll
            for (int i8 = 0; i8 < 8; i8++) {
                ull x2 = pack2(in8[i8]);
#pragma unroll
                for (int p = 0; p < 8; p++)
                    acc[p] = fma2(x2, w1a[i8 * 8 + p], acc[p]);
            }
            __half2 hp[8];
#pragma unroll
            for (int p = 0; p < 8; p++) {
                float a, b;
                unpack2(acc[p], a, b);
                hp[p] = __floats2half2_rn(a, (p < 7) ? b : 0.f);
            }
            uint4 q0, q1;
            q0.x = *(unsigned*)&hp[0]; q0.y = *(unsigned*)&hp[1];
            q0.z = *(unsigned*)&hp[2]; q0.w = *(unsigned*)&hp[3];
            q1.x = *(unsigned*)&hp[4]; q1.y = *(unsigned*)&hp[5];
            q1.z = *(unsigned*)&hp[6]; q1.w = *(unsigned*)&hp[7];
            g_pre1h[i * 2]     = q0;
            g_pre1h[i * 2 + 1] = q1;
            g_sa[i] = make_int2(src[e], __float_as_int(avals[e]));
            g_rowp[i] = rows[e];
        }
    }
    gsync();

    // phase 7: block-relative segment metadata (localrow | segoff | tail)
    {
        const int lane = tid & 31;
        const int w = tid >> 5;
        int e0 = g_part[bid], e1 = g_part[bid + 1];
        int nb0 = bid * NODE_CHUNK;
        int ngr = (e1 - e0 + 31) >> 5;
        for (int kk = w; kk < ngr; kk += WPB) {
            int e = e0 + kk * 32 + lane;
            bool valid = (e < e1);
            int el = valid ? e : (e1 - 1);
            int r = g_rowp[el];
            int reff = valid ? r : (-1 - lane);   // invalid lanes: unique rows
            int prev = __shfl_up_sync(FULLM, reff, 1);
            bool head = (lane == 0) || (reff != prev);
            unsigned hm = __ballot_sync(FULLM, head);
            unsigned below = hm & (FULLM >> (31 - lane));
            int segoff = lane - (31 - __clz(below));
            bool tail = (lane == 31) || ((hm >> (lane + 1)) & 1u);
            if (valid)
                g_rowp[e] = (r - nb0) | (segoff << 18) | (tail ? (1 << 23) : 0);
        }
    }
}

// ===== persistent main kernel: block-local scatter, ONE barrier/iter =====
__global__ __launch_bounds__(NTHR, 1)
void gnn_main_k(const float* __restrict__ st0,
                const float* __restrict__ old0,
                float* __restrict__ out, int write_num) {
    __shared__ float sacc[NODE_CHUNK * 8];   // 21632 B block-local accumulator
    const int tid = threadIdx.x;
    const int bid = blockIdx.x;
    const int lane = tid & 31;
    const int w = tid >> 5;

    const int e0 = __ldg(&g_part[bid]);
    const int e1 = __ldg(&g_part[bid + 1]);
    const int ngr = (e1 - e0 + 31) >> 5;

    const int myNode = bid * NODE_CHUNK + tid;
    const bool owner = (tid < NODE_CHUNK) && (myNode < N_NODES);
    float s[5], o[5];
    for (int i = tid; i < NODE_CHUNK * 8; i += NTHR) sacc[i] = 0.f;
    {
        int f = 0;
        if (owner) {
            float ss = 0.f;
#pragma unroll
            for (int i = 0; i < 5; i++) {
                s[i] = st0[myNode * 5 + i];
                o[i] = old0[myNode * 5 + i];
                float d = s[i] - o[i];
                ss += d * d;
            }
            __half2 p01 = __floats2half2_rn(s[0], s[1]);
            __half2 p23 = __floats2half2_rn(s[2], s[3]);
            __half2 p4  = __floats2half2_rn(s[4], 0.f);
            uint4 sv;
            sv.x = *(unsigned*)&p01; sv.y = *(unsigned*)&p23;
            sv.z = *(unsigned*)&p4;  sv.w = 0u;
            __stcg(&g_stateh[myNode], sv);
            if (sqrtf(ss + 1e-11f) > THRESH) f = 1;
        }
        int anyf = __syncthreads_or(f);
        if (tid == 0 && anyf) atomicOr(&g_flag_arr[0], 1);
    }
    gsync();

    const ull* w1s = (const ull*)cw.W1s;
    const ull* w2u = (const ull*)cw.W2u;

    int k = 0;
    for (int it = 0; it < MAX_ITER; ++it) {
        if (__ldcg(&g_flag_arr[it]) == 0) break;
        k++;

        // ===== edge phase over own range: d1 full prefetch (R11 body) =====
        int kg = w;
        int2 sa = make_int2(0, 0);
        int rp = 0;
        uint4 sv = make_uint4(0, 0, 0, 0);
        uint4 pr0 = make_uint4(0, 0, 0, 0);
        uint4 pr1 = make_uint4(0, 0, 0, 0);
        if (kg < ngr) {
            int e = e0 + kg * 32 + lane;
            int el = (e < e1) ? e : (e1 - 1);
            sa = __ldg(&g_sa[el]);
            rp = __ldg(&g_rowp[el]);
            pr0 = __ldg(&g_pre1h[el * 2]);
            pr1 = __ldg(&g_pre1h[el * 2 + 1]);
            sv = __ldcg(&g_stateh[sa.x]);
        }
        while (kg < ngr) {
            int kn = kg + WPB;

            uint4 cp0 = pr0, cp1 = pr1;
            uint4 csv = sv;
            bool vc = (e0 + kg * 32 + lane) < e1;
            int crp = vc ? rp : 0;
            float cav = vc ? __int_as_float(sa.y) : 0.f;
            if (kn < ngr) {
                int en = e0 + kn * 32 + lane;
                int eln = (en < e1) ? en : (e1 - 1);
                sa = __ldg(&g_sa[eln]);
                rp = __ldg(&g_rowp[eln]);
                pr0 = __ldg(&g_pre1h[eln * 2]);
                pr1 = __ldg(&g_pre1h[eln * 2 + 1]);
                sv = __ldcg(&g_stateh[sa.x]);
            }

            float2 p01 = __half22float2(*(__half2*)&csv.x);
            float2 p23 = __half22float2(*(__half2*)&csv.y);
            float2 p4  = __half22float2(*(__half2*)&csv.z);
            float sx[5] = {p01.x, p01.y, p23.x, p23.y, p4.x};

            // layer 1: acc = pre1 + state @ W1[8:13]
            const __half2* ph0 = (const __half2*)&cp0;
            const __half2* ph1 = (const __half2*)&cp1;
            ull acc[8];
#pragma unroll
            for (int p = 0; p < 4; p++) {
                float2 f = __half22float2(ph0[p]);
                acc[p] = pack2f(f.x, f.y);
            }
#pragma unroll
            for (int p = 0; p < 4; p++) {
                float2 f = __half22float2(ph1[p]);
                acc[4 + p] = pack2f(f.x, f.y);
            }
#pragma unroll
            for (int i = 0; i < 5; i++) {
                ull x2 = pack2(sx[i]);
#pragma unroll
                for (int p = 0; p < 8; p++)
                    acc[p] = fma2(x2, w1s[i * 8 + p], acc[p]);
            }

            // tanh (1 MUFU each) + layer 2
            ull z[5];
#pragma unroll
            for (int kk = 0; kk < 5; kk++) z[kk] = pack2f(cw.B2[kk], 0.f);
#pragma unroll
            for (int p = 0; p < 8; p++) {
                float a, b;
                unpack2(acc[p], a, b);
                float ta = tanha(a);
                float tb = tanha(b);   // p==7 hi is 0 -> tanh(0)=0, weight 0
                ull hp = pack2f(ta, tb);
#pragma unroll
                for (int kk = 0; kk < 5; kk++)
                    z[kk] = fma2(hp, w2u[p * 5 + kk], z[kk]);
            }
            // layer-2 tanh (1 MUFU each) + arc weight
            float v0, v1, v2, v3, v4;
            {
                float lo, hi;
                unpack2(z[0], lo, hi); v0 = tanha(lo + hi) * cav;
                unpack2(z[1], lo, hi); v1 = tanha(lo + hi) * cav;
                unpack2(z[2], lo, hi); v2 = tanha(lo + hi) * cav;
                unpack2(z[3], lo, hi); v3 = tanha(lo + hi) * cav;
                unpack2(z[4], lo, hi); v4 = tanha(lo + hi) * cav;
            }

            // segmented inclusive scan over sorted rows (packed)
            int segoff = (crp >> 18) & 31;
            ull v01 = pack2f(v0, v1);
            ull v23 = pack2f(v2, v3);
#pragma unroll
            for (int d = 1; d < 32; d <<= 1) {
                ull t01 = __shfl_up_sync(FULLM, v01, d);
                ull t23 = __shfl_up_sync(FULLM, v23, d);
                float t4 = __shfl_up_sync(FULLM, v4, d);
                if (segoff >= d) { v01 = add2(v01, t01); v23 = add2(v23, t23); v4 += t4; }
            }
            if (crp & (1 << 23)) {
                int lr = crp & 0x3FFFF;        // local row
                float a0, a1, a2, a3;
                unpack2(v01, a0, a1);
                unpack2(v23, a2, a3);
                float* ap = &sacc[lr * 8];
                atomicAdd(ap + 0, a0);
                atomicAdd(ap + 1, a1);
                atomicAdd(ap + 2, a2);
                atomicAdd(ap + 3, a3);
                atomicAdd(ap + 4, v4);
            }
            kg = kn;
        }

        // ===== node phase: block-local commit from smem, then ONE gsync =====
        __syncthreads();
        {
            int f = 0;
            if (owner) {
                float a0 = sacc[tid * 8 + 0];
                float a1 = sacc[tid * 8 + 1];
                float a2 = sacc[tid * 8 + 2];
                float a3 = sacc[tid * 8 + 3];
                float a4 = sacc[tid * 8 + 4];
                sacc[tid * 8 + 0] = 0.f;
                sacc[tid * 8 + 1] = 0.f;
                sacc[tid * 8 + 2] = 0.f;
                sacc[tid * 8 + 3] = 0.f;
                sacc[tid * 8 + 4] = 0.f;
                o[0] = s[0]; o[1] = s[1]; o[2] = s[2]; o[3] = s[3]; o[4] = s[4];
                s[0] = a0; s[1] = a1; s[2] = a2; s[3] = a3; s[4] = a4;
                __half2 p01 = __floats2half2_rn(s[0], s[1]);
                __half2 p23 = __floats2half2_rn(s[2], s[3]);
                __half2 p4  = __floats2half2_rn(s[4], 0.f);
                uint4 svw;
                svw.x = *(unsigned*)&p01; svw.y = *(unsigned*)&p23;
                svw.z = *(unsigned*)&p4;  svw.w = 0u;
                __stcg(&g_stateh[myNode], svw);
                float ss = 0.f;
#pragma unroll
                for (int i = 0; i < 5; i++) { float d = s[i] - o[i]; ss += d * d; }
                if (sqrtf(ss + 1e-11f) > THRESH) f = 1;
            }
            int anyf = __syncthreads_or(f);
            if (tid == 0 && anyf) atomicOr(&g_flag_arr[it + 1], 1);
        }
        gsync();
    }

    // ===== readout (precise) =====
    if (owner) {
        float h[10];
#pragma unroll
        for (int j = 0; j < 10; j++) {
            float a = cw.B3[j];
#pragma unroll
            for (int i = 0; i < 5; i++) a += s[i] * cw.W3[i * 10 + j];
            h[j] = tanhf(a);
        }
        float l[7];
        float m = -1e30f;
#pragma unroll
        for (int c = 0; c < 7; c++) {
            float a = cw.B4[c];
#pragma unroll
            for (int j = 0; j < 10; j++) a += h[j] * cw.W4[j * 7 + c];
            l[c] = a;
            m = fmaxf(m, a);
        }
        float sum = 0.f;
#pragma unroll
        for (int c = 0; c < 7; c++) { float ev = expf(l[c] - m); l[c] = ev; sum += ev; }
        float inv = 1.0f / sum;
#pragma unroll
        for (int c = 0; c < 7; c++) out[(size_t)myNode * 7 + c] = l[c] * inv;
    }
    if (bid == 0 && tid == 0 && write_num) out[(size_t)N_NODES * 7] = (float)k;
}

extern "C" void kernel_launch(void* const* d_in, const int* in_sizes, int n_in,
                              void* d_out, int out_size) {
    const float* edge_feat = (const float*)d_in[0];
    const int*   edge_src  = (const int*)d_in[1];
    const int*   arc_rows  = (const int*)d_in[2];
    const float* arc_vals  = (const float*)d_in[3];
    const float* st0       = (const float*)d_in[4];
    const float* old0      = (const float*)d_in[5];
    const float* W1        = (const float*)d_in[6];
    const float* b1        = (const float*)d_in[7];
    const float* W2        = (const float*)d_in[8];
    const float* b2        = (const float*)d_in[9];
    const float* W3        = (const float*)d_in[10];
    const float* b3        = (const float*)d_in[11];
    const float* W4        = (const float*)d_in[12];
    const float* b4        = (const float*)d_in[13];
    float* out = (float*)d_out;

    build_k<<<NBLK, NTHR>>>(edge_feat, edge_src, arc_rows, arc_vals,
                            W1, b1, W2, b2, W3, b3, W4, b4);

    void *pCW, *pStage;
    cudaGetSymbolAddress(&pCW, cw);
    cudaGetSymbolAddress(&pStage, g_stage);
    cudaMemcpyAsync(pCW, pStage, sizeof(CW), cudaMemcpyDeviceToDevice, 0);

    gnn_main_k<<<NBLK, NTHR>>>(st0, old0, out, (out_size > N_NODES * 7) ? 1 : 0);
}